// round 10
// baseline (speedup 1.0000x reference)
#include <cuda_runtime.h>
#include <math.h>

#define N_    4096
#define B_    16
#define NT_   500
#define GRID_ 128
#define TPB_  512
#define NSLICE 32
#define KSL   128   // k per slice (NSLICE*KSL == N_)

// ---------------- persistent device state (allowed: __device__ globals) ----
__device__ float g_Wt[(size_t)N_ * N_];          // Wt[k*N_ + n] = W[n*N_ + k]   (64 MB)
__device__ float g_Yp[N_ * B_];                  // Yp[k*B_ + b]                 (256 KB)
__device__ float g_Zpart[(size_t)NSLICE * B_ * N_]; // [slice][b][n]             (8 MB)
__device__ unsigned g_count = 0;
__device__ unsigned g_sense = 0;
__device__ unsigned g_anyspike = 0;              // set if any spike can occur

typedef unsigned long long u64;

// ---------------- packed f32x2 helpers (Blackwell FFMA2: PTX-only) --------
__device__ __forceinline__ u64 pack2(float x) {
    u64 r; asm("mov.b64 %0, {%1, %1};" : "=l"(r) : "f"(x)); return r;
}
__device__ __forceinline__ void fma2(u64& d, u64 a, u64 b) {
    asm("fma.rn.f32x2 %0, %1, %2, %0;" : "+l"(d) : "l"(a), "l"(b));
}
// L2-only loads for cross-SM-mutated data (L1 not coherent within a
// persistent kernel -> .cg is load-bearing for correctness)
__device__ __forceinline__ float4 ldcg4(const float* p) {
    float4 v;
    asm("ld.global.cg.v4.f32 {%0,%1,%2,%3}, [%4];"
        : "=f"(v.x), "=f"(v.y), "=f"(v.z), "=f"(v.w) : "l"(p));
    return v;
}
__device__ __forceinline__ float ldcg(const float* p) {
    float v; asm("ld.global.cg.f32 %0, [%1];" : "=f"(v) : "l"(p)); return v;
}
__device__ __forceinline__ unsigned ldcgu(const unsigned* p) {
    unsigned v; asm("ld.global.cg.u32 %0, [%1];" : "=r"(v) : "l"(p)); return v;
}

// ---------------- grid-wide sense-reversing barrier (slow path only) -------
__device__ __forceinline__ void grid_barrier(unsigned& lsense) {
    __syncthreads();
    if (threadIdx.x == 0) {
        unsigned s = lsense ^ 1u;
        __threadfence();
        if (atomicAdd(&g_count, 1u) == GRID_ - 1u) {
            atomicExch(&g_count, 0u);
            __threadfence();
            atomicExch(&g_sense, s);
        } else {
            volatile unsigned* gs = &g_sense;
            while (*gs != s) { }
            __threadfence();
        }
        lsense = s;
    }
    __syncthreads();
}

// ================= kernel 1: analytic spike test + zero-write ==============
// The Euler map g(V)=V+0.1*f(V), f(V)=(-(V-EL)+e^{V-VT}+Z)/tau, has
// g'(V)=0.99+0.01*e^{V+55} > 0: strictly monotone increasing, so iterates
// can never cross a fixed point (a root of f). With Y0 == 0, Z = x0 is
// constant, hence per neuron:
//   - f(V0) <= 0  -> V decreases monotonically -> no spike ever.
//   - f(V0) >  0  -> V rises, but if a root of f exists in (V0, VTH) it is an
//     impassable (attracting-from-below) barrier. Roots exist iff
//     Z <= max_V h(V), h(V)=V-EL-e^{V-VT}, whose max over V<=VTH is 16 at
//     V=VT=-55. So V0 <= -55 and Z <= 15.5 guarantees a barrier above V0.
// No spikes -> S == 0 -> Y stays exactly 0 -> Z stays exactly x0 (induction),
// so the hypothesis is self-validating and r == 0 exactly. Margins 0.01/0.5
// absorb fp32 rounding; any violation (incl. Y0 != 0) sets the flag and the
// full dense simulator runs (overwriting the zeros written here).
//
// Ordering: the PDL trigger fires right after the flag atomics -- K2 only
// depends on the flag. The zero-stores happen after the trigger; they are
// complete by K1 retirement, and nothing reads `out` until the graph (fast
// path: harness) or until ~ms later (slow path: sim epilogue overwrite).
__global__ void __launch_bounds__(128, 1)
check_kernel(const float* __restrict__ x0, const float* __restrict__ V0,
             const float* __restrict__ Y0, float* __restrict__ out)
{
    const int i4 = (blockIdx.x * 128 + threadIdx.x) * 4;   // 0..65532 step 4
    const float4 yv = *reinterpret_cast<const float4*>(Y0 + i4);
    const float4 xv = *reinterpret_cast<const float4*>(x0 + i4);
    const float4 Vv = *reinterpret_cast<const float4*>(V0 + i4);

    bool unsafe = false;
    {
        const float h0 = Vv.x + 72.0f - expf(Vv.x + 55.0f);
        unsafe |= !(yv.x == 0.0f && (xv.x <= h0 - 0.01f || (Vv.x <= -55.0f && xv.x <= 15.5f)));
    }
    {
        const float h0 = Vv.y + 72.0f - expf(Vv.y + 55.0f);
        unsafe |= !(yv.y == 0.0f && (xv.y <= h0 - 0.01f || (Vv.y <= -55.0f && xv.y <= 15.5f)));
    }
    {
        const float h0 = Vv.z + 72.0f - expf(Vv.z + 55.0f);
        unsafe |= !(yv.z == 0.0f && (xv.z <= h0 - 0.01f || (Vv.z <= -55.0f && xv.z <= 15.5f)));
    }
    {
        const float h0 = Vv.w + 72.0f - expf(Vv.w + 55.0f);
        unsafe |= !(yv.w == 0.0f && (xv.w <= h0 - 0.01f || (Vv.w <= -55.0f && xv.w <= 15.5f)));
    }

    if (__any_sync(0xFFFFFFFFu, unsafe)) {
        if ((threadIdx.x & 31) == 0) atomicOr(&g_anyspike, 1u);
    }

    // Release the secondary kernel: the flag (K2's only dependency) is final.
    cudaTriggerProgrammaticLaunchCompletion();

    // Unconditional zero-write: exact result on fast path, harmlessly
    // overwritten (ms later, by the same-index thread) on slow path.
    *reinterpret_cast<float4*>(out + i4) = make_float4(0.f, 0.f, 0.f, 0.f);
}

// ================= kernel 2: gated full simulator ==========================
// Launched with programmatic stream serialization: its CTAs may be scheduled
// while check_kernel still runs; they wait in cudaGridDependencySynchronize()
// (a no-op if launched without PDL). Fast path (flag == 0): out already holds
// the proved-exact zeros -> return immediately. Slow path: full dense fp32
// simulation (verified rounds 1-5, byte-identical since).
__global__ void __launch_bounds__(TPB_, 1)
snn_kernel(const float* __restrict__ W, const float* __restrict__ x0,
           const float* __restrict__ V0, const float* __restrict__ Y0,
           float* __restrict__ out)
{
    cudaGridDependencySynchronize();         // wait for check_kernel's flag
    if (ldcgu(&g_anyspike) == 0u) return;    // fast path: nothing to do

    // Y staged in smem: 2 slices x 128 k x 16 b  (16 KB)
    __shared__ float Ys[2 * KSL * B_];
    __shared__ float tile[32][33];

    const int g = blockIdx.x;
    const int t = threadIdx.x;
    unsigned lsense = 0;

    // ---- per-thread neuron identity ----
    const int u  = g * TPB_ + t;            // 0..65535
    const int nn = u & (N_ - 1);            // neuron index
    const int bb = u >> 12;                 // batch index

    // ---- init A: tiled transpose W -> g_Wt (coalesced both sides) ----
    {
        const int TPR = N_ / 32;            // 128 tiles per side
        const int i = t >> 5, j = t & 31;   // 16 rows x 32 cols per pass
        for (int tt = g; tt < TPR * TPR; tt += GRID_) {
            const int trow = tt / TPR;      // n-block
            const int tcol = tt % TPR;      // k-block
            #pragma unroll
            for (int r = 0; r < 32; r += 16)
                tile[r + i][j] = W[(size_t)(trow * 32 + r + i) * N_ + tcol * 32 + j];
            __syncthreads();
            #pragma unroll
            for (int r = 0; r < 32; r += 16)
                g_Wt[(size_t)(tcol * 32 + r + i) * N_ + trow * 32 + j] = tile[j][r + i];
            __syncthreads();
        }
    }

    // ---- init B: pack Y0 -> Yp[k][b]  (65536 = GRID_*TPB_ exactly) ----
    {
        const int m = g * TPB_ + t;
        const int k = m >> 4, b = m & 15;
        g_Yp[m] = Y0[b * N_ + k];
    }

    // ---- per-thread neuron state, registers for 500 steps ----
    float Vr = V0[bb * N_ + nn];
    float Yr = Y0[bb * N_ + nn];
    const float xr = x0[bb * N_ + nn];
    float Rr = 0.0f;

    // ---- GEMM task mapping ----
    const int nt = g >> 4;
    const int sg = g & 15;
    const int ng = t & 255;
    const int h  = t >> 8;
    const int n0 = nt * 512 + ng * 2;       // this thread's n pair
    const int sl = 2 * sg + h;              // k-slice 0..31
    const float* wt_base = g_Wt + (size_t)sl * KSL * N_ + n0;
    const float* yg      = g_Yp + 2 * sg * KSL * B_;   // 16 KB (2 slices)
    const float* ysm     = Ys + h * (KSL * B_);
    float* zbase = g_Zpart + (size_t)sl * B_ * N_ + n0;

    grid_barrier(lsense);                        // init done (1)

    const float cY    = (float)(0.1 / 8.0);         // dt / tausyn
    const float scale = (float)(0.1 / (500 * 0.1)); // dt / T

    for (int step = 0; step < NT_; ++step) {
        // ---- stage this block's 2 Y slices into smem (coalesced, L2 reads)
        #pragma unroll
        for (int i = 0; i < (2 * KSL * B_) / (4 * TPB_); ++i) {  // 2 float4/thr
            const int idx = (i * TPB_ + t) * 4;
            const float4 v = ldcg4(yg + idx);
            *reinterpret_cast<float4*>(&Ys[idx]) = v;
        }
        __syncthreads();

        // ======== phase 1: partial GEMM (2 n x 16 b, 128 k) ====
        u64 A0[8], A1[8];
        #pragma unroll
        for (int j = 0; j < 8; ++j) { A0[j] = 0ull; A1[j] = 0ull; }

        #pragma unroll 8
        for (int kk = 0; kk < KSL; ++kk) {
            const float2 w2 = *reinterpret_cast<const float2*>(wt_base + (size_t)kk * N_);
            const u64 wp0 = pack2(w2.x);
            const u64 wp1 = pack2(w2.y);
            const ulonglong2* yrow = reinterpret_cast<const ulonglong2*>(ysm + kk * B_);
            const ulonglong2 p0 = yrow[0];
            const ulonglong2 p1 = yrow[1];
            const ulonglong2 p2 = yrow[2];
            const ulonglong2 p3 = yrow[3];
            fma2(A0[0], wp0, p0.x); fma2(A1[0], wp1, p0.x);
            fma2(A0[1], wp0, p0.y); fma2(A1[1], wp1, p0.y);
            fma2(A0[2], wp0, p1.x); fma2(A1[2], wp1, p1.x);
            fma2(A0[3], wp0, p1.y); fma2(A1[3], wp1, p1.y);
            fma2(A0[4], wp0, p2.x); fma2(A1[4], wp1, p2.x);
            fma2(A0[5], wp0, p2.y); fma2(A1[5], wp1, p2.y);
            fma2(A0[6], wp0, p3.x); fma2(A1[6], wp1, p3.x);
            fma2(A0[7], wp0, p3.y); fma2(A1[7], wp1, p3.y);
        }
        // store partials: Zpart[sl][b][n0..n1], 16 coalesced STG.64
        {
            union F2 { u64 u; float2 f; };
            #pragma unroll
            for (int j = 0; j < 8; ++j) {
                F2 a{A0[j]}, b{A1[j]};
                *reinterpret_cast<float2*>(zbase + (size_t)(2 * j) * N_) =
                    make_float2(a.f.x, b.f.x);
                *reinterpret_cast<float2*>(zbase + (size_t)(2 * j + 1) * N_) =
                    make_float2(a.f.y, b.f.y);
            }
        }

        grid_barrier(lsense);                    // partials visible

        // ======== phase 2: neuron update (1 item, state in registers) ====
        {
            float Z = xr;
            #pragma unroll
            for (int s2 = 0; s2 < NSLICE; ++s2)
                Z += ldcg(g_Zpart + ((size_t)s2 * B_ + bb) * N_ + nn);
            float num = -(Vr - (-72.0f));
            num = num + expf(Vr - (-55.0f));
            num = num + Z;
            const float dV = num / 10.0f;
            float Vn = Vr + 0.1f * dV;
            Vn = fmaxf(Vn, -85.0f);
            const bool sp2 = (Vn >= 0.0f);
            const float S = sp2 ? 10.0f : 0.0f;
            if (sp2) Vn = -72.0f;
            Vr = Vn;
            Yr = Yr + cY * (S - Yr);
            Rr += S;
            g_Yp[nn * B_ + bb] = Yr;
        }

        grid_barrier(lsense);                    // Yp visible for next step
    }

    // ---- output: r * dt/T  (layout out[b][n], coalesced) ----
    out[bb * N_ + nn] = Rr * scale;

    grid_barrier(lsense);   // pad: total slow-path barriers = 1+1000+1 = 1002 (even)

    // hygiene: restore flag for next replay (re-derived deterministically)
    if (g == 0 && t == 0) g_anyspike = 0u;
}

extern "C" void kernel_launch(void* const* d_in, const int* in_sizes, int n_in,
                              void* d_out, int out_size)
{
    (void)in_sizes; (void)n_in; (void)out_size;
    const float* W  = (const float*)d_in[0];
    const float* x0 = (const float*)d_in[1];
    const float* V0 = (const float*)d_in[2];
    const float* Y0 = (const float*)d_in[3];

    check_kernel<<<128, 128>>>(x0, V0, Y0, (float*)d_out);

    // PDL launch: snn_kernel's CTAs may be scheduled while check_kernel runs;
    // cudaGridDependencySynchronize() inside orders the flag writes.
    cudaLaunchConfig_t cfg = {};
    cfg.gridDim  = dim3(GRID_);
    cfg.blockDim = dim3(TPB_);
    cfg.dynamicSmemBytes = 0;
    cfg.stream = 0;   // same default stream this TU's <<<>>> resolves to
    cudaLaunchAttribute at[1];
    at[0].id = cudaLaunchAttributeProgrammaticStreamSerialization;
    at[0].val.programmaticStreamSerializationAllowed = 1;
    cfg.attrs = at;
    cfg.numAttrs = 1;
    cudaLaunchKernelEx(&cfg, snn_kernel, W, x0, V0, Y0, (float*)d_out);
}

// round 11
// speedup vs baseline: 1.0435x; 1.0435x over previous
#include <cuda_runtime.h>
#include <math.h>

#define N_    4096
#define B_    16
#define NT_   500
#define GRID_ 128
#define TPB_  512
#define NSLICE 32
#define KSL   128   // k per slice (NSLICE*KSL == N_)

// ---------------- persistent device state (allowed: __device__ globals) ----
__device__ float g_Wt[(size_t)N_ * N_];          // Wt[k*N_ + n] = W[n*N_ + k]   (64 MB)
__device__ float g_Yp[N_ * B_];                  // Yp[k*B_ + b]                 (256 KB)
__device__ float g_Zpart[(size_t)NSLICE * B_ * N_]; // [slice][b][n]             (8 MB)
__device__ unsigned g_count = 0;
__device__ unsigned g_sense = 0;
__device__ unsigned g_anyspike = 0;              // set if any spike can occur

typedef unsigned long long u64;

// ---------------- packed f32x2 helpers (Blackwell FFMA2: PTX-only) --------
__device__ __forceinline__ u64 pack2(float x) {
    u64 r; asm("mov.b64 %0, {%1, %1};" : "=l"(r) : "f"(x)); return r;
}
__device__ __forceinline__ void fma2(u64& d, u64 a, u64 b) {
    asm("fma.rn.f32x2 %0, %1, %2, %0;" : "+l"(d) : "l"(a), "l"(b));
}
// L2-only loads for cross-SM-mutated data (L1 not coherent within a
// persistent kernel -> .cg is load-bearing for correctness)
__device__ __forceinline__ float4 ldcg4(const float* p) {
    float4 v;
    asm("ld.global.cg.v4.f32 {%0,%1,%2,%3}, [%4];"
        : "=f"(v.x), "=f"(v.y), "=f"(v.z), "=f"(v.w) : "l"(p));
    return v;
}
__device__ __forceinline__ float ldcg(const float* p) {
    float v; asm("ld.global.cg.f32 %0, [%1];" : "=f"(v) : "l"(p)); return v;
}
__device__ __forceinline__ unsigned ldcgu(const unsigned* p) {
    unsigned v; asm("ld.global.cg.u32 %0, [%1];" : "=r"(v) : "l"(p)); return v;
}

// ---------------- grid-wide sense-reversing barrier (slow path only) -------
__device__ __forceinline__ void grid_barrier(unsigned& lsense) {
    __syncthreads();
    if (threadIdx.x == 0) {
        unsigned s = lsense ^ 1u;
        __threadfence();
        if (atomicAdd(&g_count, 1u) == GRID_ - 1u) {
            atomicExch(&g_count, 0u);
            __threadfence();
            atomicExch(&g_sense, s);
        } else {
            volatile unsigned* gs = &g_sense;
            while (*gs != s) { }
            __threadfence();
        }
        lsense = s;
    }
    __syncthreads();
}

// ================= kernel 1: analytic spike test + zero-write ==============
// The Euler map g(V)=V+0.1*f(V), f(V)=(-(V-EL)+e^{V-VT}+Z)/tau, has
// g'(V)=0.99+0.01*e^{V+55} > 0: strictly monotone increasing, so iterates
// can never cross a fixed point (a root of f). With Y0 == 0, Z = x0 is
// constant, hence per neuron:
//   - f(V0) <= 0  -> V decreases monotonically -> no spike ever.
//   - f(V0) >  0  -> V rises, but if a root of f exists in (V0, VTH) it is an
//     impassable (attracting-from-below) barrier. Roots exist iff
//     Z <= max_V h(V), h(V)=V-EL-e^{V-VT}, whose max over V<=VTH is 16 at
//     V=VT=-55. So V0 <= -55 and Z <= 15.5 guarantees a barrier above V0.
// No spikes -> S == 0 -> Y stays exactly 0 -> Z stays exactly x0 (induction),
// so the hypothesis is self-validating and r == 0 exactly. The 0.01 / 0.5
// margins exceed fp32 + __expf (~2^-22 rel) evaluation error by >3 orders of
// magnitude; any violation (incl. Y0 != 0) sets the flag and the full dense
// simulator runs (overwriting the zeros written here).
//
// Ordering: the PDL trigger fires right after the flag atomics -- K2 only
// depends on the flag. The zero-stores follow the trigger; they complete by
// K1 retirement, and nothing reads `out` until graph completion (fast path)
// or the sim epilogue overwrite ~ms later (slow path).
__global__ void __launch_bounds__(256, 1)
check_kernel(const float* __restrict__ x0, const float* __restrict__ V0,
             const float* __restrict__ Y0, float* __restrict__ out)
{
    const int i4 = (blockIdx.x * 256 + threadIdx.x) * 4;   // 0..65532 step 4
    const float4 yv = *reinterpret_cast<const float4*>(Y0 + i4);
    const float4 xv = *reinterpret_cast<const float4*>(x0 + i4);
    const float4 Vv = *reinterpret_cast<const float4*>(V0 + i4);

    bool unsafe = false;
    {
        const float h0 = Vv.x + 72.0f - __expf(Vv.x + 55.0f);
        unsafe |= !(yv.x == 0.0f && (xv.x <= h0 - 0.01f || (Vv.x <= -55.0f && xv.x <= 15.5f)));
    }
    {
        const float h0 = Vv.y + 72.0f - __expf(Vv.y + 55.0f);
        unsafe |= !(yv.y == 0.0f && (xv.y <= h0 - 0.01f || (Vv.y <= -55.0f && xv.y <= 15.5f)));
    }
    {
        const float h0 = Vv.z + 72.0f - __expf(Vv.z + 55.0f);
        unsafe |= !(yv.z == 0.0f && (xv.z <= h0 - 0.01f || (Vv.z <= -55.0f && xv.z <= 15.5f)));
    }
    {
        const float h0 = Vv.w + 72.0f - __expf(Vv.w + 55.0f);
        unsafe |= !(yv.w == 0.0f && (xv.w <= h0 - 0.01f || (Vv.w <= -55.0f && xv.w <= 15.5f)));
    }

    if (__any_sync(0xFFFFFFFFu, unsafe)) {
        if ((threadIdx.x & 31) == 0) atomicOr(&g_anyspike, 1u);
    }

    // Release the secondary kernel: the flag (K2's only dependency) is final.
    cudaTriggerProgrammaticLaunchCompletion();

    // Unconditional zero-write: exact result on fast path, harmlessly
    // overwritten (ms later, by the same-index thread) on slow path.
    *reinterpret_cast<float4*>(out + i4) = make_float4(0.f, 0.f, 0.f, 0.f);
}

// ================= kernel 2: gated full simulator ==========================
// Launched with programmatic stream serialization: its CTAs may be scheduled
// while check_kernel still runs; they wait in cudaGridDependencySynchronize()
// (a no-op if launched without PDL). Fast path (flag == 0): out already holds
// the proved-exact zeros -> return immediately. Slow path: full dense fp32
// simulation (verified rounds 1-5, byte-identical since).
__global__ void __launch_bounds__(TPB_, 1)
snn_kernel(const float* __restrict__ W, const float* __restrict__ x0,
           const float* __restrict__ V0, const float* __restrict__ Y0,
           float* __restrict__ out)
{
    cudaGridDependencySynchronize();         // wait for check_kernel's flag
    if (ldcgu(&g_anyspike) == 0u) return;    // fast path: nothing to do

    // Y staged in smem: 2 slices x 128 k x 16 b  (16 KB)
    __shared__ float Ys[2 * KSL * B_];
    __shared__ float tile[32][33];

    const int g = blockIdx.x;
    const int t = threadIdx.x;
    unsigned lsense = 0;

    // ---- per-thread neuron identity ----
    const int u  = g * TPB_ + t;            // 0..65535
    const int nn = u & (N_ - 1);            // neuron index
    const int bb = u >> 12;                 // batch index

    // ---- init A: tiled transpose W -> g_Wt (coalesced both sides) ----
    {
        const int TPR = N_ / 32;            // 128 tiles per side
        const int i = t >> 5, j = t & 31;   // 16 rows x 32 cols per pass
        for (int tt = g; tt < TPR * TPR; tt += GRID_) {
            const int trow = tt / TPR;      // n-block
            const int tcol = tt % TPR;      // k-block
            #pragma unroll
            for (int r = 0; r < 32; r += 16)
                tile[r + i][j] = W[(size_t)(trow * 32 + r + i) * N_ + tcol * 32 + j];
            __syncthreads();
            #pragma unroll
            for (int r = 0; r < 32; r += 16)
                g_Wt[(size_t)(tcol * 32 + r + i) * N_ + trow * 32 + j] = tile[j][r + i];
            __syncthreads();
        }
    }

    // ---- init B: pack Y0 -> Yp[k][b]  (65536 = GRID_*TPB_ exactly) ----
    {
        const int m = g * TPB_ + t;
        const int k = m >> 4, b = m & 15;
        g_Yp[m] = Y0[b * N_ + k];
    }

    // ---- per-thread neuron state, registers for 500 steps ----
    float Vr = V0[bb * N_ + nn];
    float Yr = Y0[bb * N_ + nn];
    const float xr = x0[bb * N_ + nn];
    float Rr = 0.0f;

    // ---- GEMM task mapping ----
    const int nt = g >> 4;
    const int sg = g & 15;
    const int ng = t & 255;
    const int h  = t >> 8;
    const int n0 = nt * 512 + ng * 2;       // this thread's n pair
    const int sl = 2 * sg + h;              // k-slice 0..31
    const float* wt_base = g_Wt + (size_t)sl * KSL * N_ + n0;
    const float* yg      = g_Yp + 2 * sg * KSL * B_;   // 16 KB (2 slices)
    const float* ysm     = Ys + h * (KSL * B_);
    float* zbase = g_Zpart + (size_t)sl * B_ * N_ + n0;

    grid_barrier(lsense);                        // init done (1)

    const float cY    = (float)(0.1 / 8.0);         // dt / tausyn
    const float scale = (float)(0.1 / (500 * 0.1)); // dt / T

    for (int step = 0; step < NT_; ++step) {
        // ---- stage this block's 2 Y slices into smem (coalesced, L2 reads)
        #pragma unroll
        for (int i = 0; i < (2 * KSL * B_) / (4 * TPB_); ++i) {  // 2 float4/thr
            const int idx = (i * TPB_ + t) * 4;
            const float4 v = ldcg4(yg + idx);
            *reinterpret_cast<float4*>(&Ys[idx]) = v;
        }
        __syncthreads();

        // ======== phase 1: partial GEMM (2 n x 16 b, 128 k) ====
        u64 A0[8], A1[8];
        #pragma unroll
        for (int j = 0; j < 8; ++j) { A0[j] = 0ull; A1[j] = 0ull; }

        #pragma unroll 8
        for (int kk = 0; kk < KSL; ++kk) {
            const float2 w2 = *reinterpret_cast<const float2*>(wt_base + (size_t)kk * N_);
            const u64 wp0 = pack2(w2.x);
            const u64 wp1 = pack2(w2.y);
            const ulonglong2* yrow = reinterpret_cast<const ulonglong2*>(ysm + kk * B_);
            const ulonglong2 p0 = yrow[0];
            const ulonglong2 p1 = yrow[1];
            const ulonglong2 p2 = yrow[2];
            const ulonglong2 p3 = yrow[3];
            fma2(A0[0], wp0, p0.x); fma2(A1[0], wp1, p0.x);
            fma2(A0[1], wp0, p0.y); fma2(A1[1], wp1, p0.y);
            fma2(A0[2], wp0, p1.x); fma2(A1[2], wp1, p1.x);
            fma2(A0[3], wp0, p1.y); fma2(A1[3], wp1, p1.y);
            fma2(A0[4], wp0, p2.x); fma2(A1[4], wp1, p2.x);
            fma2(A0[5], wp0, p2.y); fma2(A1[5], wp1, p2.y);
            fma2(A0[6], wp0, p3.x); fma2(A1[6], wp1, p3.x);
            fma2(A0[7], wp0, p3.y); fma2(A1[7], wp1, p3.y);
        }
        // store partials: Zpart[sl][b][n0..n1], 16 coalesced STG.64
        {
            union F2 { u64 u; float2 f; };
            #pragma unroll
            for (int j = 0; j < 8; ++j) {
                F2 a{A0[j]}, b{A1[j]};
                *reinterpret_cast<float2*>(zbase + (size_t)(2 * j) * N_) =
                    make_float2(a.f.x, b.f.x);
                *reinterpret_cast<float2*>(zbase + (size_t)(2 * j + 1) * N_) =
                    make_float2(a.f.y, b.f.y);
            }
        }

        grid_barrier(lsense);                    // partials visible

        // ======== phase 2: neuron update (1 item, state in registers) ====
        {
            float Z = xr;
            #pragma unroll
            for (int s2 = 0; s2 < NSLICE; ++s2)
                Z += ldcg(g_Zpart + ((size_t)s2 * B_ + bb) * N_ + nn);
            float num = -(Vr - (-72.0f));
            num = num + expf(Vr - (-55.0f));
            num = num + Z;
            const float dV = num / 10.0f;
            float Vn = Vr + 0.1f * dV;
            Vn = fmaxf(Vn, -85.0f);
            const bool sp2 = (Vn >= 0.0f);
            const float S = sp2 ? 10.0f : 0.0f;
            if (sp2) Vn = -72.0f;
            Vr = Vn;
            Yr = Yr + cY * (S - Yr);
            Rr += S;
            g_Yp[nn * B_ + bb] = Yr;
        }

        grid_barrier(lsense);                    // Yp visible for next step
    }

    // ---- output: r * dt/T  (layout out[b][n], coalesced) ----
    out[bb * N_ + nn] = Rr * scale;

    grid_barrier(lsense);   // pad: total slow-path barriers = 1+1000+1 = 1002 (even)

    // hygiene: restore flag for next replay (re-derived deterministically)
    if (g == 0 && t == 0) g_anyspike = 0u;
}

extern "C" void kernel_launch(void* const* d_in, const int* in_sizes, int n_in,
                              void* d_out, int out_size)
{
    (void)in_sizes; (void)n_in; (void)out_size;
    const float* W  = (const float*)d_in[0];
    const float* x0 = (const float*)d_in[1];
    const float* V0 = (const float*)d_in[2];
    const float* Y0 = (const float*)d_in[3];

    check_kernel<<<64, 256>>>(x0, V0, Y0, (float*)d_out);

    // PDL launch: snn_kernel's CTAs may be scheduled while check_kernel runs;
    // cudaGridDependencySynchronize() inside orders the flag writes.
    cudaLaunchConfig_t cfg = {};
    cfg.gridDim  = dim3(GRID_);
    cfg.blockDim = dim3(TPB_);
    cfg.dynamicSmemBytes = 0;
    cfg.stream = 0;   // same default stream this TU's <<<>>> resolves to
    cudaLaunchAttribute at[1];
    at[0].id = cudaLaunchAttributeProgrammaticStreamSerialization;
    at[0].val.programmaticStreamSerializationAllowed = 1;
    cfg.attrs = at;
    cfg.numAttrs = 1;
    cudaLaunchKernelEx(&cfg, snn_kernel, W, x0, V0, Y0, (float*)d_out);
}